// round 12
// baseline (speedup 1.0000x reference)
#include <cuda_runtime.h>
#include <math.h>
#include <stdint.h>

#define Bc 8
#define Sc 2048
#define Dc 1024
#define Hc 4
#define HDc 256
#define NCTA 128
#define ROWS_PER_CTA 128
#define RING 3
#define NSTAGE_ALL 32            // 16 stats stages + 16 output stages (same data)
#define NTHR 512

// dynamic smem layout (bytes):
//   [0, 16384)        combine scratch (4096 floats)
//   [16384, 18432)    row stats: 128 x float4
//   [18432, 215040)   ring: 3 slots x (2 tensors x 8 rows x 1024 f) = 192 KB
//   [215040, +)       3 mbarriers
#define SCR_OFF 0
#define RS_OFF 16384
#define RING_OFF 18432
#define STAGE_FLOATS 16384
#define MBAR_OFF (RING_OFF + RING * STAGE_FLOATS * 4)   // 215040
#define SMEM_BYTES (MBAR_OFF + 64)

// ---------------- scratch (static device memory; no allocation) -------------
__device__ float  g_partial[NCTA * 2048];
__device__ float  g_simpart[NCTA];
__device__ float  g_sums[Bc * 2048];
__device__ float  g_globalsim[Bc];
__device__ float  g_gates[Bc * Hc * HDc];
__device__ unsigned g_barcnt = 0;
__device__ unsigned g_bargen = 0;

__device__ __forceinline__ float bfly(float v) {
#pragma unroll
    for (int o = 16; o > 0; o >>= 1) v += __shfl_xor_sync(0xffffffffu, v, o);
    return v;
}

__device__ __forceinline__ uint32_t smem_u32(const void* p) {
    uint32_t a;
    asm("{ .reg .u64 t; cvta.to.shared.u64 t, %1; cvt.u32.u64 %0, t; }" : "=r"(a) : "l"(p));
    return a;
}
__device__ __forceinline__ void mbar_init(uint32_t a, uint32_t cnt) {
    asm volatile("mbarrier.init.shared.b64 [%0], %1;" :: "r"(a), "r"(cnt) : "memory");
}
__device__ __forceinline__ void mbar_expect_tx(uint32_t a, uint32_t bytes) {
    asm volatile("mbarrier.arrive.expect_tx.shared.b64 _, [%0], %1;" :: "r"(a), "r"(bytes) : "memory");
}
__device__ __forceinline__ void bulk_g2s(uint32_t dst, const void* src, uint32_t bytes, uint32_t mbar) {
    asm volatile("cp.async.bulk.shared::cluster.global.mbarrier::complete_tx::bytes [%0], [%1], %2, [%3];"
                 :: "r"(dst), "l"(src), "r"(bytes), "r"(mbar) : "memory");
}
__device__ __forceinline__ void mbar_wait(uint32_t a, uint32_t parity) {
    uint32_t done;
    asm volatile(
        "{\n\t.reg .pred p;\n\t"
        "mbarrier.try_wait.parity.acquire.cta.shared::cta.b64 p, [%1], %2;\n\t"
        "selp.b32 %0, 1, 0, p;\n\t}"
        : "=r"(done) : "r"(a), "r"(parity) : "memory");
    if (!done) {
        asm volatile(
            "{\n\t.reg .pred P1;\n\t"
            "W%=:\n\t"
            "mbarrier.try_wait.parity.acquire.cta.shared::cta.b64 P1, [%0], %1, 0x989680;\n\t"
            "@P1 bra.uni D%=;\n\t"
            "bra.uni W%=;\n\t"
            "D%=:\n\t}"
            :: "r"(a), "r"(parity) : "memory");
    }
}
__device__ __forceinline__ void quad_bar(int q) {
    asm volatile("bar.sync %0, 128;" :: "r"(q + 1) : "memory");
}

// Grid-wide barrier; all threads fence first so prior global writes are visible.
__device__ __forceinline__ void grid_barrier(unsigned nblk) {
    __threadfence();
    __syncthreads();
    if (threadIdx.x == 0) {
        const unsigned gen = atomicAdd(&g_bargen, 0u);
        if (atomicAdd(&g_barcnt, 1u) == nblk - 1u) {
            atomicExch(&g_barcnt, 0u);
            __threadfence();
            atomicAdd(&g_bargen, 1u);
        } else {
            while (atomicAdd(&g_bargen, 0u) == gen) { }
        }
        __threadfence();
    }
    __syncthreads();
}

// ---------------- single fused persistent kernel ----------------------------
__global__ void __launch_bounds__(NTHR, 1) k_fused(
    const float* __restrict__ xt, const float* __restrict__ xi,
    const float* __restrict__ ltw, const float* __restrict__ ltb,
    const float* __restrict__ liw, const float* __restrict__ lib,
    const float* __restrict__ Wa, const float* __restrict__ Wab,
    const float* __restrict__ Wq, const float* __restrict__ Wqb,
    const float* __restrict__ simw, const float* __restrict__ simb,
    const float* __restrict__ fcw, const float* __restrict__ fcb,
    float* __restrict__ out)
{
    extern __shared__ __align__(1024) char dynsm[];
    float*  scr  = reinterpret_cast<float*>(dynsm + SCR_OFF);
    float4* s_rs = reinterpret_cast<float4*>(dynsm + RS_OFF);
    float*  ring = reinterpret_cast<float*>(dynsm + RING_OFF);
    __shared__ float4 redA[4][4];
    __shared__ float4 redB[4][4];
    __shared__ float s_sim[4];
    __shared__ float red[NTHR];
    __shared__ float s_gate;

    const int tid = threadIdx.x, lane = tid & 31, warp = tid >> 5;
    const int q = warp >> 2, wq = warp & 3;           // quad, warp-in-quad
    const int bi = blockIdx.x;
    const int row0 = bi * ROWS_PER_CTA;
    const int batch = bi >> 4;
    const int cidx = wq * 32 + lane;                  // float4 col base; owns {cidx, cidx+128}

    const uint32_t smem_base = smem_u32(dynsm);
    const uint32_t ringb = smem_base + RING_OFF;
    const uint32_t mbb = smem_base + MBAR_OFF;

    // phase-1 weights in registers (8 float4)
    float4 w_t[2], b_t[2], w_i[2], b_i[2];
#pragma unroll
    for (int g = 0; g < 2; g++) {
        w_t[g] = __ldg(&reinterpret_cast<const float4*>(ltw)[cidx + g * 128]);
        b_t[g] = __ldg(&reinterpret_cast<const float4*>(ltb)[cidx + g * 128]);
        w_i[g] = __ldg(&reinterpret_cast<const float4*>(liw)[cidx + g * 128]);
        b_i[g] = __ldg(&reinterpret_cast<const float4*>(lib)[cidx + g * 128]);
    }

    if (tid == 0) {
#pragma unroll
        for (int r = 0; r < RING; r++) mbar_init(mbb + r * 8, 1);
    }
    __syncthreads();

    const float* srcT = xt + (size_t)row0 * 1024;
    const float* srcI = xi + (size_t)row0 * 1024;

    if (tid == 0) {
#pragma unroll
        for (int s = 0; s < RING; s++) {
            const uint32_t mb = mbb + s * 8;
            mbar_expect_tx(mb, 65536);
            const uint32_t dst = ringb + s * STAGE_FLOATS * 4;
            bulk_g2s(dst,         srcT + s * 8192, 32768, mb);
            bulk_g2s(dst + 32768, srcI + s * 8192, 32768, mb);
        }
    }

    // ================= phase 1: LN stats over 16 stages =================
    float4 vt[2], vi[2];
#pragma unroll
    for (int g = 0; g < 2; g++) {
        vt[g] = make_float4(0.f, 0.f, 0.f, 0.f);
        vi[g] = make_float4(0.f, 0.f, 0.f, 0.f);
    }
    float sim_acc = 0.f;

    for (int gs = 0; gs < 16; gs++) {
        const int slot = gs % RING;
        const int par  = (gs / RING) & 1;
        mbar_wait(mbb + slot * 8, par);
        const float* buf = ring + slot * STAGE_FLOATS;

#pragma unroll
        for (int rr = 0; rr < 2; rr++) {
            const int rlocal = q * 2 + rr;
            const float4* A4 = reinterpret_cast<const float4*>(buf + rlocal * 1024);
            const float4* C4 = reinterpret_cast<const float4*>(buf + 8192 + rlocal * 1024);

            float4 A[2], C[2];
#pragma unroll
            for (int g = 0; g < 2; g++) {
                A[g] = A4[cidx + g * 128];
                C[g] = C4[cidx + g * 128];
            }

            float sa = 0.f, saa = 0.f, sc = 0.f, scc = 0.f;
#pragma unroll
            for (int g = 0; g < 2; g++) {
                sa += A[g].x; saa = fmaf(A[g].x, A[g].x, saa);
                sa += A[g].y; saa = fmaf(A[g].y, A[g].y, saa);
                sa += A[g].z; saa = fmaf(A[g].z, A[g].z, saa);
                sa += A[g].w; saa = fmaf(A[g].w, A[g].w, saa);
                sc += C[g].x; scc = fmaf(C[g].x, C[g].x, scc);
                sc += C[g].y; scc = fmaf(C[g].y, C[g].y, scc);
                sc += C[g].z; scc = fmaf(C[g].z, C[g].z, scc);
                sc += C[g].w; scc = fmaf(C[g].w, C[g].w, scc);
            }
            sa = bfly(sa); saa = bfly(saa); sc = bfly(sc); scc = bfly(scc);
            if (lane == 0) redA[q][wq] = make_float4(sa, saa, sc, scc);
            quad_bar(q);
            const float4 e0 = redA[q][0], e1 = redA[q][1], e2 = redA[q][2], e3 = redA[q][3];
            const float fsa  = (e0.x + e1.x) + (e2.x + e3.x);
            const float fsaa = (e0.y + e1.y) + (e2.y + e3.y);
            const float fsc  = (e0.z + e1.z) + (e2.z + e3.z);
            const float fscc = (e0.w + e1.w) + (e2.w + e3.w);

            const float mut = fsa * (1.f / 1024.f);
            const float rt  = rsqrtf(fmaxf(fsaa * (1.f / 1024.f) - mut * mut, 0.f) + 1e-5f);
            const float mui = fsc * (1.f / 1024.f);
            const float ri  = rsqrtf(fmaxf(fscc * (1.f / 1024.f) - mui * mui, 0.f) + 1e-5f);
            if (wq == 0 && lane == 0) s_rs[gs * 8 + rlocal] = make_float4(mut, rt, mui, ri);

            const float nmt = -rt * mut, nmi = -ri * mui;
            float tt = 0.f, ii = 0.f, ti = 0.f;
#pragma unroll
            for (int g = 0; g < 2; g++) {
                float f, h2, tn, in;
                f  = fmaf(A[g].x, rt, nmt);  tn = fmaf(f, w_t[g].x, b_t[g].x);
                h2 = fmaf(C[g].x, ri, nmi);  in = fmaf(h2, w_i[g].x, b_i[g].x);
                tt = fmaf(tn, tn, tt); ii = fmaf(in, in, ii); ti = fmaf(tn, in, ti);
                vt[g].x += tn; vi[g].x += in;

                f  = fmaf(A[g].y, rt, nmt);  tn = fmaf(f, w_t[g].y, b_t[g].y);
                h2 = fmaf(C[g].y, ri, nmi);  in = fmaf(h2, w_i[g].y, b_i[g].y);
                tt = fmaf(tn, tn, tt); ii = fmaf(in, in, ii); ti = fmaf(tn, in, ti);
                vt[g].y += tn; vi[g].y += in;

                f  = fmaf(A[g].z, rt, nmt);  tn = fmaf(f, w_t[g].z, b_t[g].z);
                h2 = fmaf(C[g].z, ri, nmi);  in = fmaf(h2, w_i[g].z, b_i[g].z);
                tt = fmaf(tn, tn, tt); ii = fmaf(in, in, ii); ti = fmaf(tn, in, ti);
                vt[g].z += tn; vi[g].z += in;

                f  = fmaf(A[g].w, rt, nmt);  tn = fmaf(f, w_t[g].w, b_t[g].w);
                h2 = fmaf(C[g].w, ri, nmi);  in = fmaf(h2, w_i[g].w, b_i[g].w);
                tt = fmaf(tn, tn, tt); ii = fmaf(in, in, ii); ti = fmaf(tn, in, ti);
                vt[g].w += tn; vi[g].w += in;
            }
            tt = bfly(tt); ii = bfly(ii); ti = bfly(ti);
            if (lane == 0) redB[q][wq] = make_float4(tt, ii, ti, 0.f);
            quad_bar(q);
            if (wq == 0) {
                const float4 d0 = redB[q][0], d1 = redB[q][1], d2 = redB[q][2], d3 = redB[q][3];
                const float ftt = (d0.x + d1.x) + (d2.x + d3.x);
                const float fii = (d0.y + d1.y) + (d2.y + d3.y);
                const float fti = (d0.z + d1.z) + (d2.z + d3.z);
                sim_acc += fti / (fmaxf(sqrtf(ftt), 1e-6f) * fmaxf(sqrtf(fii), 1e-6f));
            }
        }

        __syncthreads();   // all quads done with this slot
        if (tid == 0 && gs + RING < NSTAGE_ALL) {
            const int k = (gs + RING) & 15;
            const uint32_t mb = mbb + slot * 8;
            mbar_expect_tx(mb, 65536);
            const uint32_t dst = ringb + slot * STAGE_FLOATS * 4;
            bulk_g2s(dst,         srcT + k * 8192, 32768, mb);
            bulk_g2s(dst + 32768, srcI + k * 8192, 32768, mb);
        }
    }

    // ---- combine partial sums ----
    if (wq == 0 && lane == 0) s_sim[q] = sim_acc;
    __syncthreads();
    float4* slice = reinterpret_cast<float4*>(scr + (q & 1) * 2048);
    if (q < 2) {
#pragma unroll
        for (int g = 0; g < 2; g++) {
            slice[cidx + g * 128]       = vt[g];
            slice[256 + cidx + g * 128] = vi[g];
        }
    }
    __syncthreads();
    if (q >= 2) {
#pragma unroll
        for (int g = 0; g < 2; g++) {
            float4 v = slice[cidx + g * 128];
            v.x += vt[g].x; v.y += vt[g].y; v.z += vt[g].z; v.w += vt[g].w;
            slice[cidx + g * 128] = v;
            float4 u = slice[256 + cidx + g * 128];
            u.x += vi[g].x; u.y += vi[g].y; u.z += vi[g].z; u.w += vi[g].w;
            slice[256 + cidx + g * 128] = u;
        }
    }
    __syncthreads();
    for (int j = tid; j < 2048; j += NTHR)
        g_partial[bi * 2048 + j] = scr[j] + scr[2048 + j];
    if (tid == 0)
        g_simpart[bi] = (s_sim[0] + s_sim[1]) + (s_sim[2] + s_sim[3]);

    grid_barrier(NCTA);   // GB1: partials visible

    // ---- midA: fold partials -> g_sums; sim -> g_globalsim ----
    {
        const int j = bi * 128 + (tid & 127);
        const int quarter = tid >> 7;                 // 0..3
        const int b = j >> 11, slot = j & 2047;
        float s = 0.f;
#pragma unroll
        for (int p = quarter * 4; p < quarter * 4 + 4; p++)
            s += g_partial[(b * 16 + p) * 2048 + slot];
        red[tid] = s;
        __syncthreads();
        if (tid < 128)
            g_sums[j] = ((red[tid] + red[tid + 128]) + (red[tid + 256] + red[tid + 384]))
                        * (1.f / (float)Sc);
    }
    if (bi == 0 && warp < 8) {
        float v = (lane < 16) ? g_simpart[warp * 16 + lane] : 0.f;
        v = bfly(v);
        if (lane == 0) g_globalsim[warp] = v * (1.f / (float)Sc);
    }

    grid_barrier(NCTA);   // GB2: g_sums visible

    // ---- midB: gate GEMV; 16 warps = 8 hk x 2 batch-halves ----
    {
        const int w8 = warp & 7;
        const int bh = warp >> 3;                     // batch half 0/1
        const int hk = bi * 8 + w8;
        const int kk = hk & 255;
        const float4* wa = reinterpret_cast<const float4*>(Wa + (size_t)hk * 1024);
        const float4* wq4 = reinterpret_cast<const float4*>(Wq + (size_t)hk * 1024);
        float4 wA[8], wQ[8];
#pragma unroll
        for (int g = 0; g < 8; g++) {
            wA[g] = __ldg(&wa[g * 32 + lane]);
            wQ[g] = __ldg(&wq4[g * 32 + lane]);
        }
        float da[4], dq[4];
#pragma unroll
        for (int b = 0; b < 4; b++) { da[b] = 0.f; dq[b] = 0.f; }
#pragma unroll
        for (int b = 0; b < 4; b++) {
            const int bb = bh * 4 + b;
            const float4* tg = reinterpret_cast<const float4*>(g_sums + bb * 2048);
            const float4* ig = tg + 256;
#pragma unroll
            for (int g = 0; g < 8; g++) {
                const float4 t = tg[g * 32 + lane];
                const float4 i = ig[g * 32 + lane];
                da[b] = fmaf(wA[g].x, t.x, da[b]); da[b] = fmaf(wA[g].y, t.y, da[b]);
                da[b] = fmaf(wA[g].z, t.z, da[b]); da[b] = fmaf(wA[g].w, t.w, da[b]);
                dq[b] = fmaf(wQ[g].x, i.x, dq[b]); dq[b] = fmaf(wQ[g].y, i.y, dq[b]);
                dq[b] = fmaf(wQ[g].z, i.z, dq[b]); dq[b] = fmaf(wQ[g].w, i.w, dq[b]);
            }
        }
#pragma unroll
        for (int b = 0; b < 4; b++) { da[b] = bfly(da[b]); dq[b] = bfly(dq[b]); }
        if (lane == 0) {
            const float wab = Wab[hk], wqb = Wqb[hk];
            const float sw = simw[kk], sb = simb[kk];
#pragma unroll
            for (int b = 0; b < 4; b++) {
                const int bb = bh * 4 + b;
                const float gate = da[b] + wab + dq[b] + wqb + g_globalsim[bb] * sw + sb;
                g_gates[bb * 1024 + hk] = fmaxf(gate, 0.f);
            }
        }
    }

    grid_barrier(NCTA);   // GB3: g_gates visible

    // ---- local fc (CTA computes its own batch's gate; deterministic) ----
    {
        float acc = 0.f;
#pragma unroll
        for (int k = tid; k < 1024; k += NTHR) acc += g_gates[batch * 1024 + k] * fcw[k];
        acc = bfly(acc);
        if (lane == 0) red[warp] = acc;
        __syncthreads();
        if (tid == 0) {
            float s = 0.f;
#pragma unroll
            for (int w = 0; w < 16; w++) s += red[w];
            s_gate = 1.0f / (1.0f + expf(-(s + fcb[0])));
        }
        __syncthreads();
    }
    const float gg = s_gate, gm = 1.0f - gg;

    // phase-3 weights (loaded only now: not live during phase 1)
    const int col = tid & 255;
    const int sub = tid >> 8;                         // 0/1: row split
    const float4 wt3 = __ldg(&reinterpret_cast<const float4*>(ltw)[col]);
    const float4 bt3 = __ldg(&reinterpret_cast<const float4*>(ltb)[col]);
    const float4 wi3 = __ldg(&reinterpret_cast<const float4*>(liw)[col]);
    const float4 bi3 = __ldg(&reinterpret_cast<const float4*>(lib)[col]);

    // ================= phase 3: output blend over 16 stages =================
    float4* out4 = reinterpret_cast<float4*>(out);
    for (int gs = 16; gs < 32; gs++) {
        const int slot = gs % RING;
        const int par  = (gs / RING) & 1;
        mbar_wait(mbb + slot * 8, par);
        const float* buf = ring + slot * STAGE_FLOATS;
        const int p3s = gs - 16;

#pragma unroll
        for (int it = 0; it < 4; it++) {
            const int r = it * 2 + sub;
            const int ridx = p3s * 8 + r;
            const float4 rs = s_rs[ridx];
            const float4 a = reinterpret_cast<const float4*>(buf + r * 1024)[col];
            const float4 c = reinterpret_cast<const float4*>(buf + 8192 + r * 1024)[col];
            float4 o;
            o.x = gg * ((a.x - rs.x) * rs.y * wt3.x + bt3.x) + gm * ((c.x - rs.z) * rs.w * wi3.x + bi3.x);
            o.y = gg * ((a.y - rs.x) * rs.y * wt3.y + bt3.y) + gm * ((c.y - rs.z) * rs.w * wi3.y + bi3.y);
            o.z = gg * ((a.z - rs.x) * rs.y * wt3.z + bt3.z) + gm * ((c.z - rs.z) * rs.w * wi3.z + bi3.z);
            o.w = gg * ((a.w - rs.x) * rs.y * wt3.w + bt3.w) + gm * ((c.w - rs.z) * rs.w * wi3.w + bi3.w);
            __stcs(&out4[(size_t)(row0 + ridx) * 256 + col], o);
        }
        __syncthreads();
        if (tid == 0 && gs + RING < NSTAGE_ALL) {
            const int k = (gs + RING) & 15;
            const uint32_t mb = mbb + slot * 8;
            mbar_expect_tx(mb, 65536);
            const uint32_t dst = ringb + slot * STAGE_FLOATS * 4;
            bulk_g2s(dst,         srcT + k * 8192, 32768, mb);
            bulk_g2s(dst + 32768, srcI + k * 8192, 32768, mb);
        }
    }
}

// ---------------- launch -----------------------------------------------------
extern "C" void kernel_launch(void* const* d_in, const int* in_sizes, int n_in,
                              void* d_out, int out_size)
{
    const float* xt   = (const float*)d_in[0];
    const float* xi   = (const float*)d_in[1];
    const float* ltw  = (const float*)d_in[2];
    const float* ltb  = (const float*)d_in[3];
    const float* liw  = (const float*)d_in[4];
    const float* lib  = (const float*)d_in[5];
    const float* Wa   = (const float*)d_in[6];
    const float* Wab  = (const float*)d_in[7];
    const float* Wq   = (const float*)d_in[8];
    const float* Wqb  = (const float*)d_in[9];
    const float* simw = (const float*)d_in[10];
    const float* simb = (const float*)d_in[11];
    const float* fcw  = (const float*)d_in[12];
    const float* fcb  = (const float*)d_in[13];
    float* out = (float*)d_out;

    static bool attr_set = false;
    if (!attr_set) {
        cudaFuncSetAttribute(k_fused, cudaFuncAttributeMaxDynamicSharedMemorySize, SMEM_BYTES);
        attr_set = true;
    }

    k_fused<<<NCTA, NTHR, SMEM_BYTES>>>(xt, xi, ltw, ltb, liw, lib,
                                        Wa, Wab, Wq, Wqb, simw, simb, fcw, fcb, out);
}

// round 13
// speedup vs baseline: 1.0536x; 1.0536x over previous
#include <cuda_runtime.h>
#include <math.h>
#include <stdint.h>

#define Bc 8
#define Sc 2048
#define Dc 1024
#define Hc 4
#define HDc 256
#define NCTA 128
#define ROWS_PER_CTA 128
#define RING 3
#define NSTAGE_ALL 32            // 16 stats stages + 16 output stages (same data)

// dynamic smem layout (bytes):
//   [0, 16384)        combine scratch (4096 floats)
//   [16384, 18432)    row stats: 128 x float4
//   [18432, 215040)   ring: 3 slots x (2 tensors x 8 rows x 1024 f) = 192 KB
//   [215040, +)       3 mbarriers
#define SCR_OFF 0
#define RS_OFF 16384
#define RING_OFF 18432
#define STAGE_FLOATS 16384
#define MBAR_OFF (RING_OFF + RING * STAGE_FLOATS * 4)   // 215040
#define SMEM_BYTES (MBAR_OFF + 64)

// ---------------- scratch (static device memory; no allocation) -------------
__device__ float  g_partial[NCTA * 2048];
__device__ float  g_simpart[NCTA];
__device__ float  g_sums[Bc * 2048];
__device__ float  g_globalsim[Bc];
__device__ float  g_gates[Bc * Hc * HDc];
__device__ unsigned g_barcnt = 0;
__device__ unsigned g_bargen = 0;

__device__ __forceinline__ float bfly(float v) {
#pragma unroll
    for (int o = 16; o > 0; o >>= 1) v += __shfl_xor_sync(0xffffffffu, v, o);
    return v;
}

__device__ __forceinline__ uint32_t smem_u32(const void* p) {
    uint32_t a;
    asm("{ .reg .u64 t; cvta.to.shared.u64 t, %1; cvt.u32.u64 %0, t; }" : "=r"(a) : "l"(p));
    return a;
}
__device__ __forceinline__ void mbar_init(uint32_t a, uint32_t cnt) {
    asm volatile("mbarrier.init.shared.b64 [%0], %1;" :: "r"(a), "r"(cnt) : "memory");
}
__device__ __forceinline__ void mbar_expect_tx(uint32_t a, uint32_t bytes) {
    asm volatile("mbarrier.arrive.expect_tx.shared.b64 _, [%0], %1;" :: "r"(a), "r"(bytes) : "memory");
}
__device__ __forceinline__ void bulk_g2s(uint32_t dst, const void* src, uint32_t bytes, uint32_t mbar) {
    asm volatile("cp.async.bulk.shared::cluster.global.mbarrier::complete_tx::bytes [%0], [%1], %2, [%3];"
                 :: "r"(dst), "l"(src), "r"(bytes), "r"(mbar) : "memory");
}
__device__ __forceinline__ void mbar_wait(uint32_t a, uint32_t parity) {
    uint32_t done;
    asm volatile(
        "{\n\t.reg .pred p;\n\t"
        "mbarrier.try_wait.parity.acquire.cta.shared::cta.b64 p, [%1], %2;\n\t"
        "selp.b32 %0, 1, 0, p;\n\t}"
        : "=r"(done) : "r"(a), "r"(parity) : "memory");
    if (!done) {
        asm volatile(
            "{\n\t.reg .pred P1;\n\t"
            "W%=:\n\t"
            "mbarrier.try_wait.parity.acquire.cta.shared::cta.b64 P1, [%0], %1, 0x989680;\n\t"
            "@P1 bra.uni D%=;\n\t"
            "bra.uni W%=;\n\t"
            "D%=:\n\t}"
            :: "r"(a), "r"(parity) : "memory");
    }
}

// Grid-wide barrier; all threads fence first so prior global writes are visible.
__device__ __forceinline__ void grid_barrier(unsigned nblk) {
    __threadfence();
    __syncthreads();
    if (threadIdx.x == 0) {
        const unsigned gen = atomicAdd(&g_bargen, 0u);
        if (atomicAdd(&g_barcnt, 1u) == nblk - 1u) {
            atomicExch(&g_barcnt, 0u);
            __threadfence();
            atomicAdd(&g_bargen, 1u);
        } else {
            while (atomicAdd(&g_bargen, 0u) == gen) { }
        }
        __threadfence();
    }
    __syncthreads();
}

// ---------------- single fused persistent kernel ----------------------------
__global__ void __launch_bounds__(256, 1) k_fused(
    const float* __restrict__ xt, const float* __restrict__ xi,
    const float* __restrict__ ltw, const float* __restrict__ ltb,
    const float* __restrict__ liw, const float* __restrict__ lib,
    const float* __restrict__ Wa, const float* __restrict__ Wab,
    const float* __restrict__ Wq, const float* __restrict__ Wqb,
    const float* __restrict__ simw, const float* __restrict__ simb,
    const float* __restrict__ fcw, const float* __restrict__ fcb,
    float* __restrict__ out)
{
    extern __shared__ __align__(1024) char dynsm[];
    float*  scr  = reinterpret_cast<float*>(dynsm + SCR_OFF);
    float4* s_rs = reinterpret_cast<float4*>(dynsm + RS_OFF);
    float*  ring = reinterpret_cast<float*>(dynsm + RING_OFF);
    __shared__ float4 redA[4][2];
    __shared__ float4 redB[4][2];
    __shared__ float s_sim[4];
    __shared__ float red[256];
    __shared__ float s_gate;

    const int tid = threadIdx.x, lane = tid & 31, warp = tid >> 5;
    const int pair = warp >> 1, h = warp & 1;
    const int bi = blockIdx.x;
    const int row0 = bi * ROWS_PER_CTA;
    const int batch = bi >> 4;
    const int cidx = h * 128 + lane;           // phase-1 float4 column base (+g*32)

    const uint32_t smem_base = smem_u32(dynsm);
    const uint32_t ringb = smem_base + RING_OFF;
    const uint32_t mbb = smem_base + MBAR_OFF;

    // phase-1 weights (column set cidx+g*32) in registers
    float4 w_t[4], b_t[4], w_i[4], b_i[4];
#pragma unroll
    for (int g = 0; g < 4; g++) {
        w_t[g] = __ldg(&reinterpret_cast<const float4*>(ltw)[cidx + g * 32]);
        b_t[g] = __ldg(&reinterpret_cast<const float4*>(ltb)[cidx + g * 32]);
        w_i[g] = __ldg(&reinterpret_cast<const float4*>(liw)[cidx + g * 32]);
        b_i[g] = __ldg(&reinterpret_cast<const float4*>(lib)[cidx + g * 32]);
    }

    if (tid == 0) {
#pragma unroll
        for (int r = 0; r < RING; r++) mbar_init(mbb + r * 8, 1);
    }
    __syncthreads();

    const float* srcT = xt + (size_t)row0 * 1024;
    const float* srcI = xi + (size_t)row0 * 1024;

    if (tid == 0) {
#pragma unroll
        for (int s = 0; s < RING; s++) {
            const uint32_t mb = mbb + s * 8;
            mbar_expect_tx(mb, 65536);
            const uint32_t dst = ringb + s * STAGE_FLOATS * 4;
            bulk_g2s(dst,         srcT + s * 8192, 32768, mb);
            bulk_g2s(dst + 32768, srcI + s * 8192, 32768, mb);
        }
    }

    // ================= phase 1: LN stats over 16 stages =================
    float4 vt[4], vi[4];
#pragma unroll
    for (int g = 0; g < 4; g++) {
        vt[g] = make_float4(0.f, 0.f, 0.f, 0.f);
        vi[g] = make_float4(0.f, 0.f, 0.f, 0.f);
    }
    float sim_acc = 0.f;

    for (int gs = 0; gs < 16; gs++) {
        const int slot = gs % RING;
        const int par  = (gs / RING) & 1;
        mbar_wait(mbb + slot * 8, par);
        const float* buf = ring + slot * STAGE_FLOATS;

#pragma unroll
        for (int rr = 0; rr < 2; rr++) {
            const int rlocal = pair * 2 + rr;
            const float4* A4 = reinterpret_cast<const float4*>(buf + rlocal * 1024);
            const float4* C4 = reinterpret_cast<const float4*>(buf + 8192 + rlocal * 1024);

            float4 A[4], C[4];
#pragma unroll
            for (int g = 0; g < 4; g++) {
                A[g] = A4[cidx + g * 32];
                C[g] = C4[cidx + g * 32];
            }

            float sa = 0.f, saa = 0.f, sc = 0.f, scc = 0.f;
#pragma unroll
            for (int g = 0; g < 4; g++) {
                sa += A[g].x; saa = fmaf(A[g].x, A[g].x, saa);
                sa += A[g].y; saa = fmaf(A[g].y, A[g].y, saa);
                sa += A[g].z; saa = fmaf(A[g].z, A[g].z, saa);
                sa += A[g].w; saa = fmaf(A[g].w, A[g].w, saa);
                sc += C[g].x; scc = fmaf(C[g].x, C[g].x, scc);
                sc += C[g].y; scc = fmaf(C[g].y, C[g].y, scc);
                sc += C[g].z; scc = fmaf(C[g].z, C[g].z, scc);
                sc += C[g].w; scc = fmaf(C[g].w, C[g].w, scc);
            }
            sa = bfly(sa); saa = bfly(saa); sc = bfly(sc); scc = bfly(scc);
            if (lane == 0) redA[pair][h] = make_float4(sa, saa, sc, scc);
            __syncthreads();
            const float4 e0 = redA[pair][0], e1 = redA[pair][1];
            const float mut = (e0.x + e1.x) * (1.f / 1024.f);
            const float rt  = rsqrtf(fmaxf((e0.y + e1.y) * (1.f / 1024.f) - mut * mut, 0.f) + 1e-5f);
            const float mui = (e0.z + e1.z) * (1.f / 1024.f);
            const float ri  = rsqrtf(fmaxf((e0.w + e1.w) * (1.f / 1024.f) - mui * mui, 0.f) + 1e-5f);
            if (h == 0 && lane == 0) s_rs[gs * 8 + rlocal] = make_float4(mut, rt, mui, ri);

            const float nmt = -rt * mut, nmi = -ri * mui;
            float tt = 0.f, ii = 0.f, ti = 0.f;
#pragma unroll
            for (int g = 0; g < 4; g++) {
                float f, h2, tn, in;
                f  = fmaf(A[g].x, rt, nmt);  tn = fmaf(f, w_t[g].x, b_t[g].x);
                h2 = fmaf(C[g].x, ri, nmi);  in = fmaf(h2, w_i[g].x, b_i[g].x);
                tt = fmaf(tn, tn, tt); ii = fmaf(in, in, ii); ti = fmaf(tn, in, ti);
                vt[g].x += tn; vi[g].x += in;

                f  = fmaf(A[g].y, rt, nmt);  tn = fmaf(f, w_t[g].y, b_t[g].y);
                h2 = fmaf(C[g].y, ri, nmi);  in = fmaf(h2, w_i[g].y, b_i[g].y);
                tt = fmaf(tn, tn, tt); ii = fmaf(in, in, ii); ti = fmaf(tn, in, ti);
                vt[g].y += tn; vi[g].y += in;

                f  = fmaf(A[g].z, rt, nmt);  tn = fmaf(f, w_t[g].z, b_t[g].z);
                h2 = fmaf(C[g].z, ri, nmi);  in = fmaf(h2, w_i[g].z, b_i[g].z);
                tt = fmaf(tn, tn, tt); ii = fmaf(in, in, ii); ti = fmaf(tn, in, ti);
                vt[g].z += tn; vi[g].z += in;

                f  = fmaf(A[g].w, rt, nmt);  tn = fmaf(f, w_t[g].w, b_t[g].w);
                h2 = fmaf(C[g].w, ri, nmi);  in = fmaf(h2, w_i[g].w, b_i[g].w);
                tt = fmaf(tn, tn, tt); ii = fmaf(in, in, ii); ti = fmaf(tn, in, ti);
                vt[g].w += tn; vi[g].w += in;
            }
            tt = bfly(tt); ii = bfly(ii); ti = bfly(ti);
            if (lane == 0) redB[pair][h] = make_float4(tt, ii, ti, 0.f);
            __syncthreads();
            if (h == 0) {
                const float4 d0 = redB[pair][0], d1 = redB[pair][1];
                sim_acc += (d0.z + d1.z) /
                           (fmaxf(sqrtf(d0.x + d1.x), 1e-6f) * fmaxf(sqrtf(d0.y + d1.y), 1e-6f));
            }
        }

        // reissue this slot: next use is gs+RING (phase-1 or phase-3 — same data!)
        if (tid == 0 && gs + RING < NSTAGE_ALL) {
            const int k = (gs + RING) & 15;
            const uint32_t mb = mbb + slot * 8;
            mbar_expect_tx(mb, 65536);
            const uint32_t dst = ringb + slot * STAGE_FLOATS * 4;
            bulk_g2s(dst,         srcT + k * 8192, 32768, mb);
            bulk_g2s(dst + 32768, srcI + k * 8192, 32768, mb);
        }
    }

    // ---- combine partial sums (scratch region — no ring conflict) ----
    if (h == 0 && lane == 0) s_sim[pair] = sim_acc;
    __syncthreads();
    float4* slice = reinterpret_cast<float4*>(scr + (pair & 1) * 2048);
    if (pair < 2) {
#pragma unroll
        for (int g = 0; g < 4; g++) {
            slice[cidx + g * 32]       = vt[g];
            slice[256 + cidx + g * 32] = vi[g];
        }
    }
    __syncthreads();
    if (pair >= 2) {
#pragma unroll
        for (int g = 0; g < 4; g++) {
            float4 v = slice[cidx + g * 32];
            v.x += vt[g].x; v.y += vt[g].y; v.z += vt[g].z; v.w += vt[g].w;
            slice[cidx + g * 32] = v;
            float4 u = slice[256 + cidx + g * 32];
            u.x += vi[g].x; u.y += vi[g].y; u.z += vi[g].z; u.w += vi[g].w;
            slice[256 + cidx + g * 32] = u;
        }
    }
    __syncthreads();
    for (int j = tid; j < 2048; j += 256)
        g_partial[bi * 2048 + j] = scr[j] + scr[2048 + j];
    if (tid == 0)
        g_simpart[bi] = (s_sim[0] + s_sim[1]) + (s_sim[2] + s_sim[3]);

    grid_barrier(NCTA);   // GB1: partials visible

    // ---- midA: fold partials -> g_sums; sim -> g_globalsim ----
    {
        const int j = bi * 128 + (tid & 127);
        const int half = tid >> 7;
        const int b = j >> 11, slot = j & 2047;
        float s = 0.f;
#pragma unroll
        for (int p = half * 8; p < half * 8 + 8; p++)
            s += g_partial[(b * 16 + p) * 2048 + slot];
        red[tid] = s;
        __syncthreads();
        if (tid < 128) g_sums[j] = (red[tid] + red[tid + 128]) * (1.f / (float)Sc);
    }
    if (bi == 0) {
        float v = (lane < 16) ? g_simpart[warp * 16 + lane] : 0.f;
        v = bfly(v);
        if (lane == 0) g_globalsim[warp] = v * (1.f / (float)Sc);
    }

    grid_barrier(NCTA);   // GB2: g_sums visible

    // ---- midB: gate GEMV (warp-per-hk, all 8 batches) ----
    // NOTE: g_sums/g_globalsim written this kernel -> PLAIN loads (no __ldg).
    {
        const int hk = bi * 8 + warp;
        const int kk = hk & 255;
        const float4* wa = reinterpret_cast<const float4*>(Wa + (size_t)hk * 1024);
        const float4* wq = reinterpret_cast<const float4*>(Wq + (size_t)hk * 1024);
        float4 wA[8], wQ[8];
#pragma unroll
        for (int g = 0; g < 8; g++) {
            wA[g] = __ldg(&wa[g * 32 + lane]);
            wQ[g] = __ldg(&wq[g * 32 + lane]);
        }
        float da[Bc], dq[Bc];
#pragma unroll
        for (int b = 0; b < Bc; b++) { da[b] = 0.f; dq[b] = 0.f; }
#pragma unroll
        for (int b = 0; b < Bc; b++) {
            const float4* tg = reinterpret_cast<const float4*>(g_sums + b * 2048);
            const float4* ig = tg + 256;
#pragma unroll
            for (int g = 0; g < 8; g++) {
                const float4 t = tg[g * 32 + lane];
                const float4 i = ig[g * 32 + lane];
                da[b] = fmaf(wA[g].x, t.x, da[b]); da[b] = fmaf(wA[g].y, t.y, da[b]);
                da[b] = fmaf(wA[g].z, t.z, da[b]); da[b] = fmaf(wA[g].w, t.w, da[b]);
                dq[b] = fmaf(wQ[g].x, i.x, dq[b]); dq[b] = fmaf(wQ[g].y, i.y, dq[b]);
                dq[b] = fmaf(wQ[g].z, i.z, dq[b]); dq[b] = fmaf(wQ[g].w, i.w, dq[b]);
            }
        }
#pragma unroll
        for (int b = 0; b < Bc; b++) { da[b] = bfly(da[b]); dq[b] = bfly(dq[b]); }
        if (lane == 0) {
            const float wab = Wab[hk], wqb = Wqb[hk];
            const float sw = simw[kk], sb = simb[kk];
#pragma unroll
            for (int b = 0; b < Bc; b++) {
                const float gate = da[b] + wab + dq[b] + wqb + g_globalsim[b] * sw + sb;
                g_gates[b * 1024 + hk] = fmaxf(gate, 0.f);
            }
        }
    }

    grid_barrier(NCTA);   // GB3: g_gates visible

    // ---- local fc (each CTA computes its own batch's gate; deterministic) ----
    {
        float acc = 0.f;
#pragma unroll
        for (int k = tid; k < 1024; k += 256) acc += g_gates[batch * 1024 + k] * fcw[k];
        acc = bfly(acc);
        if (lane == 0) red[warp] = acc;
        __syncthreads();
        if (tid == 0) {
            float s = 0.f;
#pragma unroll
            for (int w = 0; w < 8; w++) s += red[w];
            s_gate = 1.0f / (1.0f + expf(-(s + fcb[0])));
        }
        __syncthreads();
    }
    const float gg = s_gate, gm = 1.0f - gg;

    // phase-3 weights (loaded only now — keeps them out of phase-1 live range)
    const float4 wt3 = __ldg(&reinterpret_cast<const float4*>(ltw)[tid]);
    const float4 bt3 = __ldg(&reinterpret_cast<const float4*>(ltb)[tid]);
    const float4 wi3 = __ldg(&reinterpret_cast<const float4*>(liw)[tid]);
    const float4 bi3 = __ldg(&reinterpret_cast<const float4*>(lib)[tid]);

    // ================= phase 3: output blend over 16 stages =================
    float4* out4 = reinterpret_cast<float4*>(out);
    for (int gs = 16; gs < 32; gs++) {
        const int slot = gs % RING;
        const int par  = (gs / RING) & 1;
        mbar_wait(mbb + slot * 8, par);
        const float* buf = ring + slot * STAGE_FLOATS;
        const int p3s = gs - 16;

#pragma unroll
        for (int r = 0; r < 8; r++) {
            const int ridx = p3s * 8 + r;
            const float4 rs = s_rs[ridx];
            const float4 a = reinterpret_cast<const float4*>(buf + r * 1024)[tid];
            const float4 c = reinterpret_cast<const float4*>(buf + 8192 + r * 1024)[tid];
            float4 o;
            o.x = gg * ((a.x - rs.x) * rs.y * wt3.x + bt3.x) + gm * ((c.x - rs.z) * rs.w * wi3.x + bi3.x);
            o.y = gg * ((a.y - rs.x) * rs.y * wt3.y + bt3.y) + gm * ((c.y - rs.z) * rs.w * wi3.y + bi3.y);
            o.z = gg * ((a.z - rs.x) * rs.y * wt3.z + bt3.z) + gm * ((c.z - rs.z) * rs.w * wi3.z + bi3.z);
            o.w = gg * ((a.w - rs.x) * rs.y * wt3.w + bt3.w) + gm * ((c.w - rs.z) * rs.w * wi3.w + bi3.w);
            __stcs(&out4[(size_t)(row0 + ridx) * 256 + tid], o);
        }
        __syncthreads();
        if (tid == 0 && gs + RING < NSTAGE_ALL) {
            const int k = (gs + RING) & 15;
            const uint32_t mb = mbb + slot * 8;
            mbar_expect_tx(mb, 65536);
            const uint32_t dst = ringb + slot * STAGE_FLOATS * 4;
            bulk_g2s(dst,         srcT + k * 8192, 32768, mb);
            bulk_g2s(dst + 32768, srcI + k * 8192, 32768, mb);
        }
    }
}

// ---------------- launch -----------------------------------------------------
extern "C" void kernel_launch(void* const* d_in, const int* in_sizes, int n_in,
                              void* d_out, int out_size)
{
    const float* xt   = (const float*)d_in[0];
    const float* xi   = (const float*)d_in[1];
    const float* ltw  = (const float*)d_in[2];
    const float* ltb  = (const float*)d_in[3];
    const float* liw  = (const float*)d_in[4];
    const float* lib  = (const float*)d_in[5];
    const float* Wa   = (const float*)d_in[6];
    const float* Wab  = (const float*)d_in[7];
    const float* Wq   = (const float*)d_in[8];
    const float* Wqb  = (const float*)d_in[9];
    const float* simw = (const float*)d_in[10];
    const float* simb = (const float*)d_in[11];
    const float* fcw  = (const float*)d_in[12];
    const float* fcb  = (const float*)d_in[13];
    float* out = (float*)d_out;

    static bool attr_set = false;
    if (!attr_set) {
        cudaFuncSetAttribute(k_fused, cudaFuncAttributeMaxDynamicSharedMemorySize, SMEM_BYTES);
        attr_set = true;
    }

    k_fused<<<NCTA, 256, SMEM_BYTES>>>(xt, xi, ltw, ltb, liw, lib,
                                       Wa, Wab, Wq, Wqb, simw, simb, fcw, fcb, out);
}

// round 15
// speedup vs baseline: 1.0560x; 1.0022x over previous
#include <cuda_runtime.h>
#include <math.h>
#include <stdint.h>

#define Bc 8
#define Sc 2048
#define Dc 1024
#define Hc 4
#define HDc 256
#define NCTA 128
#define ROWS_PER_CTA 128
#define RING 3
#define NSTAGE_ALL 32            // 16 stats stages + 16 output stages (same data)

// dynamic smem layout (bytes):
//   [0, 16384)        combine scratch (4096 floats)
//   [16384, 18432)    row stats: 128 x float4
//   [18432, 215040)   ring: 3 slots x (2 tensors x 8 rows x 1024 f) = 192 KB
//   [215040, +)       3 mbarriers
#define SCR_OFF 0
#define RS_OFF 16384
#define RING_OFF 18432
#define STAGE_FLOATS 16384
#define MBAR_OFF (RING_OFF + RING * STAGE_FLOATS * 4)   // 215040
#define SMEM_BYTES (MBAR_OFF + 64)

// ---------------- scratch (static device memory; no allocation) -------------
__device__ float  g_partial[NCTA * 2048];
__device__ float  g_simpart[NCTA];
__device__ float  g_sums[Bc * 2048];
__device__ float  g_globalsim[Bc];
__device__ float  g_gates[Bc * Hc * HDc];
__device__ unsigned g_barcnt = 0;
__device__ unsigned g_bargen = 0;

__device__ __forceinline__ float bfly(float v) {
#pragma unroll
    for (int o = 16; o > 0; o >>= 1) v += __shfl_xor_sync(0xffffffffu, v, o);
    return v;
}

__device__ __forceinline__ uint32_t smem_u32(const void* p) {
    uint32_t a;
    asm("{ .reg .u64 t; cvta.to.shared.u64 t, %1; cvt.u32.u64 %0, t; }" : "=r"(a) : "l"(p));
    return a;
}
__device__ __forceinline__ void mbar_init(uint32_t a, uint32_t cnt) {
    asm volatile("mbarrier.init.shared.b64 [%0], %1;" :: "r"(a), "r"(cnt) : "memory");
}
__device__ __forceinline__ void mbar_expect_tx(uint32_t a, uint32_t bytes) {
    asm volatile("mbarrier.arrive.expect_tx.shared.b64 _, [%0], %1;" :: "r"(a), "r"(bytes) : "memory");
}
__device__ __forceinline__ void bulk_g2s(uint32_t dst, const void* src, uint32_t bytes, uint32_t mbar) {
    asm volatile("cp.async.bulk.shared::cluster.global.mbarrier::complete_tx::bytes [%0], [%1], %2, [%3];"
                 :: "r"(dst), "l"(src), "r"(bytes), "r"(mbar) : "memory");
}
__device__ __forceinline__ void mbar_wait(uint32_t a, uint32_t parity) {
    uint32_t done;
    asm volatile(
        "{\n\t.reg .pred p;\n\t"
        "mbarrier.try_wait.parity.acquire.cta.shared::cta.b64 p, [%1], %2;\n\t"
        "selp.b32 %0, 1, 0, p;\n\t}"
        : "=r"(done) : "r"(a), "r"(parity) : "memory");
    if (!done) {
        asm volatile(
            "{\n\t.reg .pred P1;\n\t"
            "W%=:\n\t"
            "mbarrier.try_wait.parity.acquire.cta.shared::cta.b64 P1, [%0], %1, 0x989680;\n\t"
            "@P1 bra.uni D%=;\n\t"
            "bra.uni W%=;\n\t"
            "D%=:\n\t}"
            :: "r"(a), "r"(parity) : "memory");
    }
}
__device__ __forceinline__ void pair_bar(int pair) {
    asm volatile("bar.sync %0, 64;" :: "r"(pair + 1) : "memory");
}

// Grid-wide barrier; all threads fence first so prior global writes are visible.
__device__ __forceinline__ void grid_barrier(unsigned nblk) {
    __threadfence();
    __syncthreads();
    if (threadIdx.x == 0) {
        const unsigned gen = atomicAdd(&g_bargen, 0u);
        if (atomicAdd(&g_barcnt, 1u) == nblk - 1u) {
            atomicExch(&g_barcnt, 0u);
            __threadfence();
            atomicAdd(&g_bargen, 1u);
        } else {
            while (atomicAdd(&g_bargen, 0u) == gen) { }
        }
        __threadfence();
    }
    __syncthreads();
}

// ---------------- single fused persistent kernel ----------------------------
__global__ void __launch_bounds__(256, 1) k_fused(
    const float* __restrict__ xt, const float* __restrict__ xi,
    const float* __restrict__ ltw, const float* __restrict__ ltb,
    const float* __restrict__ liw, const float* __restrict__ lib,
    const float* __restrict__ Wa, const float* __restrict__ Wab,
    const float* __restrict__ Wq, const float* __restrict__ Wqb,
    const float* __restrict__ simw, const float* __restrict__ simb,
    const float* __restrict__ fcw, const float* __restrict__ fcb,
    float* __restrict__ out)
{
    extern __shared__ __align__(1024) char dynsm[];
    float*  scr  = reinterpret_cast<float*>(dynsm + SCR_OFF);
    float4* s_rs = reinterpret_cast<float4*>(dynsm + RS_OFF);
    float*  ring = reinterpret_cast<float*>(dynsm + RING_OFF);
    __shared__ float4 redA[4][2][2];    // [pair][h][rr]
    __shared__ float4 redB[4][2][2];
    __shared__ float s_sim[4];
    __shared__ float red[256];
    __shared__ float s_gate;

    const int tid = threadIdx.x, lane = tid & 31, warp = tid >> 5;
    const int pair = warp >> 1, h = warp & 1;
    const int bi = blockIdx.x;
    const int row0 = bi * ROWS_PER_CTA;
    const int batch = bi >> 4;
    const int cidx = h * 128 + lane;           // phase-1 float4 column base (+g*32)

    const uint32_t smem_base = smem_u32(dynsm);
    const uint32_t ringb = smem_base + RING_OFF;
    const uint32_t mbb = smem_base + MBAR_OFF;

    // phase-1 weights (column set cidx+g*32) in registers
    float4 w_t[4], b_t[4], w_i[4], b_i[4];
#pragma unroll
    for (int g = 0; g < 4; g++) {
        w_t[g] = __ldg(&reinterpret_cast<const float4*>(ltw)[cidx + g * 32]);
        b_t[g] = __ldg(&reinterpret_cast<const float4*>(ltb)[cidx + g * 32]);
        w_i[g] = __ldg(&reinterpret_cast<const float4*>(liw)[cidx + g * 32]);
        b_i[g] = __ldg(&reinterpret_cast<const float4*>(lib)[cidx + g * 32]);
    }

    if (tid == 0) {
#pragma unroll
        for (int r = 0; r < RING; r++) mbar_init(mbb + r * 8, 1);
    }
    __syncthreads();

    const float* srcT = xt + (size_t)row0 * 1024;
    const float* srcI = xi + (size_t)row0 * 1024;

    if (tid == 0) {
#pragma unroll
        for (int s = 0; s < RING; s++) {
            const uint32_t mb = mbb + s * 8;
            mbar_expect_tx(mb, 65536);
            const uint32_t dst = ringb + s * STAGE_FLOATS * 4;
            bulk_g2s(dst,         srcT + s * 8192, 32768, mb);
            bulk_g2s(dst + 32768, srcI + s * 8192, 32768, mb);
        }
    }

    // ================= phase 1: LN stats over 16 stages =================
    float4 vt[4], vi[4];
#pragma unroll
    for (int g = 0; g < 4; g++) {
        vt[g] = make_float4(0.f, 0.f, 0.f, 0.f);
        vi[g] = make_float4(0.f, 0.f, 0.f, 0.f);
    }
    float sim_acc = 0.f;

    for (int gs = 0; gs < 16; gs++) {
        const int slot = gs % RING;
        const int par  = (gs / RING) & 1;
        mbar_wait(mbb + slot * 8, par);
        const float* buf = ring + slot * STAGE_FLOATS;

        // ---- load BOTH rows of this pair up-front ----
        float4 A[2][4], C[2][4];
#pragma unroll
        for (int rr = 0; rr < 2; rr++) {
            const int rlocal = pair * 2 + rr;
            const float4* A4 = reinterpret_cast<const float4*>(buf + rlocal * 1024);
            const float4* C4 = reinterpret_cast<const float4*>(buf + 8192 + rlocal * 1024);
#pragma unroll
            for (int g = 0; g < 4; g++) {
                A[rr][g] = A4[cidx + g * 32];
                C[rr][g] = C4[cidx + g * 32];
            }
        }

        // ---- 8 moment chains, butterflied back-to-back (pipelined) ----
        float sa[2], saa[2], sc[2], scc[2];
#pragma unroll
        for (int rr = 0; rr < 2; rr++) {
            float a1 = 0.f, a2 = 0.f, c1 = 0.f, c2 = 0.f;
#pragma unroll
            for (int g = 0; g < 4; g++) {
                a1 += A[rr][g].x; a2 = fmaf(A[rr][g].x, A[rr][g].x, a2);
                a1 += A[rr][g].y; a2 = fmaf(A[rr][g].y, A[rr][g].y, a2);
                a1 += A[rr][g].z; a2 = fmaf(A[rr][g].z, A[rr][g].z, a2);
                a1 += A[rr][g].w; a2 = fmaf(A[rr][g].w, A[rr][g].w, a2);
                c1 += C[rr][g].x; c2 = fmaf(C[rr][g].x, C[rr][g].x, c2);
                c1 += C[rr][g].y; c2 = fmaf(C[rr][g].y, C[rr][g].y, c2);
                c1 += C[rr][g].z; c2 = fmaf(C[rr][g].z, C[rr][g].z, c2);
                c1 += C[rr][g].w; c2 = fmaf(C[rr][g].w, C[rr][g].w, c2);
            }
            sa[rr] = a1; saa[rr] = a2; sc[rr] = c1; scc[rr] = c2;
        }
#pragma unroll
        for (int rr = 0; rr < 2; rr++) {
            sa[rr] = bfly(sa[rr]); saa[rr] = bfly(saa[rr]);
            sc[rr] = bfly(sc[rr]); scc[rr] = bfly(scc[rr]);
        }
        if (lane == 0) {
            redA[pair][h][0] = make_float4(sa[0], saa[0], sc[0], scc[0]);
            redA[pair][h][1] = make_float4(sa[1], saa[1], sc[1], scc[1]);
        }
        pair_bar(pair);

        float mut[2], rt[2], mui[2], ri[2];
#pragma unroll
        for (int rr = 0; rr < 2; rr++) {
            const float4 e0 = redA[pair][0][rr], e1 = redA[pair][1][rr];
            mut[rr] = (e0.x + e1.x) * (1.f / 1024.f);
            rt[rr]  = rsqrtf(fmaxf((e0.y + e1.y) * (1.f / 1024.f) - mut[rr] * mut[rr], 0.f) + 1e-5f);
            mui[rr] = (e0.z + e1.z) * (1.f / 1024.f);
            ri[rr]  = rsqrtf(fmaxf((e0.w + e1.w) * (1.f / 1024.f) - mui[rr] * mui[rr], 0.f) + 1e-5f);
            if (h == 0 && lane == 0)
                s_rs[gs * 8 + pair * 2 + rr] = make_float4(mut[rr], rt[rr], mui[rr], ri[rr]);
        }

        // ---- normalize both rows, accumulate; 6 dot chains back-to-back ----
        float tt[2], ii[2], ti[2];
#pragma unroll
        for (int rr = 0; rr < 2; rr++) {
            const float nmt = -rt[rr] * mut[rr], nmi = -ri[rr] * mui[rr];
            float t1 = 0.f, t2 = 0.f, t3 = 0.f;
#pragma unroll
            for (int g = 0; g < 4; g++) {
                float f, h2, tn, in;
                f  = fmaf(A[rr][g].x, rt[rr], nmt);  tn = fmaf(f, w_t[g].x, b_t[g].x);
                h2 = fmaf(C[rr][g].x, ri[rr], nmi);  in = fmaf(h2, w_i[g].x, b_i[g].x);
                t1 = fmaf(tn, tn, t1); t2 = fmaf(in, in, t2); t3 = fmaf(tn, in, t3);
                vt[g].x += tn; vi[g].x += in;

                f  = fmaf(A[rr][g].y, rt[rr], nmt);  tn = fmaf(f, w_t[g].y, b_t[g].y);
                h2 = fmaf(C[rr][g].y, ri[rr], nmi);  in = fmaf(h2, w_i[g].y, b_i[g].y);
                t1 = fmaf(tn, tn, t1); t2 = fmaf(in, in, t2); t3 = fmaf(tn, in, t3);
                vt[g].y += tn; vi[g].y += in;

                f  = fmaf(A[rr][g].z, rt[rr], nmt);  tn = fmaf(f, w_t[g].z, b_t[g].z);
                h2 = fmaf(C[rr][g].z, ri[rr], nmi);  in = fmaf(h2, w_i[g].z, b_i[g].z);
                t1 = fmaf(tn, tn, t1); t2 = fmaf(in, in, t2); t3 = fmaf(tn, in, t3);
                vt[g].z += tn; vi[g].z += in;

                f  = fmaf(A[rr][g].w, rt[rr], nmt);  tn = fmaf(f, w_t[g].w, b_t[g].w);
                h2 = fmaf(C[rr][g].w, ri[rr], nmi);  in = fmaf(h2, w_i[g].w, b_i[g].w);
                t1 = fmaf(tn, tn, t1); t2 = fmaf(in, in, t2); t3 = fmaf(tn, in, t3);
                vt[g].w += tn; vi[g].w += in;
            }
            tt[rr] = t1; ii[rr] = t2; ti[rr] = t3;
        }
#pragma unroll
        for (int rr = 0; rr < 2; rr++) {
            tt[rr] = bfly(tt[rr]); ii[rr] = bfly(ii[rr]); ti[rr] = bfly(ti[rr]);
        }
        if (lane == 0) {
            redB[pair][h][0] = make_float4(tt[0], ii[0], ti[0], 0.f);
            redB[pair][h][1] = make_float4(tt[1], ii[1], ti[1], 0.f);
        }
        pair_bar(pair);
        if (h == 0) {
#pragma unroll
            for (int rr = 0; rr < 2; rr++) {
                const float4 d0 = redB[pair][0][rr], d1 = redB[pair][1][rr];
                sim_acc += (d0.z + d1.z) /
                           (fmaxf(sqrtf(d0.x + d1.x), 1e-6f) * fmaxf(sqrtf(d0.y + d1.y), 1e-6f));
            }
        }

        __syncthreads();   // all pairs done with this slot
        // reissue this slot: next use is gs+RING (phase-1 or phase-3 — same data!)
        if (tid == 0 && gs + RING < NSTAGE_ALL) {
            const int k = (gs + RING) & 15;
            const uint32_t mb = mbb + slot * 8;
            mbar_expect_tx(mb, 65536);
            const uint32_t dst = ringb + slot * STAGE_FLOATS * 4;
            bulk_g2s(dst,         srcT + k * 8192, 32768, mb);
            bulk_g2s(dst + 32768, srcI + k * 8192, 32768, mb);
        }
    }

    // ---- combine partial sums (scratch region — no ring conflict) ----
    if (h == 0 && lane == 0) s_sim[pair] = sim_acc;
    __syncthreads();
    float4* slice = reinterpret_cast<float4*>(scr + (pair & 1) * 2048);
    if (pair < 2) {
#pragma unroll
        for (int g = 0; g < 4; g++) {
            slice[cidx + g * 32]       = vt[g];
            slice[256 + cidx + g * 32] = vi[g];
        }
    }
    __syncthreads();
    if (pair >= 2) {
#pragma unroll
        for (int g = 0; g < 4; g++) {
            float4 v = slice[cidx + g * 32];
            v.x += vt[g].x; v.y += vt[g].y; v.z += vt[g].z; v.w += vt[g].w;
            slice[cidx + g * 32] = v;
            float4 u = slice[256 + cidx + g * 32];
            u.x += vi[g].x; u.y += vi[g].y; u.z += vi[g].z; u.w += vi[g].w;
            slice[256 + cidx + g * 32] = u;
        }
    }
    __syncthreads();
    for (int j = tid; j < 2048; j += 256)
        g_partial[bi * 2048 + j] = scr[j] + scr[2048 + j];
    if (tid == 0)
        g_simpart[bi] = (s_sim[0] + s_sim[1]) + (s_sim[2] + s_sim[3]);

    grid_barrier(NCTA);   // GB1: partials visible

    // ---- midA: fold partials -> g_sums; sim -> g_globalsim ----
    {
        const int j = bi * 128 + (tid & 127);
        const int half = tid >> 7;
        const int b = j >> 11, slot = j & 2047;
        float s = 0.f;
#pragma unroll
        for (int p = half * 8; p < half * 8 + 8; p++)
            s += g_partial[(b * 16 + p) * 2048 + slot];
        red[tid] = s;
        __syncthreads();
        if (tid < 128) g_sums[j] = (red[tid] + red[tid + 128]) * (1.f / (float)Sc);
    }
    if (bi == 0) {
        float v = (lane < 16) ? g_simpart[warp * 16 + lane] : 0.f;
        v = bfly(v);
        if (lane == 0) g_globalsim[warp] = v * (1.f / (float)Sc);
    }

    grid_barrier(NCTA);   // GB2: g_sums visible

    // ---- midB: gate GEMV (warp-per-hk, all 8 batches) ----
    // g_sums/g_globalsim written this kernel -> PLAIN loads (no __ldg).
    {
        const int hk = bi * 8 + warp;
        const int kk = hk & 255;
        const float4* wa = reinterpret_cast<const float4*>(Wa + (size_t)hk * 1024);
        const float4* wq = reinterpret_cast<const float4*>(Wq + (size_t)hk * 1024);
        float4 wA[8], wQ[8];
#pragma unroll
        for (int g = 0; g < 8; g++) {
            wA[g] = __ldg(&wa[g * 32 + lane]);
            wQ[g] = __ldg(&wq[g * 32 + lane]);
        }
        float da[Bc], dq[Bc];
#pragma unroll
        for (int b = 0; b < Bc; b++) { da[b] = 0.f; dq[b] = 0.f; }
#pragma unroll
        for (int b = 0; b < Bc; b++) {
            const float4* tg = reinterpret_cast<const float4*>(g_sums + b * 2048);
            const float4* ig = tg + 256;
#pragma unroll
            for (int g = 0; g < 8; g++) {
                const float4 t = tg[g * 32 + lane];
                const float4 i = ig[g * 32 + lane];
                da[b] = fmaf(wA[g].x, t.x, da[b]); da[b] = fmaf(wA[g].y, t.y, da[b]);
                da[b] = fmaf(wA[g].z, t.z, da[b]); da[b] = fmaf(wA[g].w, t.w, da[b]);
                dq[b] = fmaf(wQ[g].x, i.x, dq[b]); dq[b] = fmaf(wQ[g].y, i.y, dq[b]);
                dq[b] = fmaf(wQ[g].z, i.z, dq[b]); dq[b] = fmaf(wQ[g].w, i.w, dq[b]);
            }
        }
#pragma unroll
        for (int b = 0; b < Bc; b++) { da[b] = bfly(da[b]); dq[b] = bfly(dq[b]); }
        if (lane == 0) {
            const float wab = Wab[hk], wqb = Wqb[hk];
            const float sw = simw[kk], sb = simb[kk];
#pragma unroll
            for (int b = 0; b < Bc; b++) {
                const float gate = da[b] + wab + dq[b] + wqb + g_globalsim[b] * sw + sb;
                g_gates[b * 1024 + hk] = fmaxf(gate, 0.f);
            }
        }
    }

    grid_barrier(NCTA);   // GB3: g_gates visible

    // ---- local fc (each CTA computes its own batch's gate; deterministic) ----
    {
        float acc = 0.f;
#pragma unroll
        for (int k = tid; k < 1024; k += 256) acc += g_gates[batch * 1024 + k] * fcw[k];
        acc = bfly(acc);
        if (lane == 0) red[warp] = acc;
        __syncthreads();
        if (tid == 0) {
            float s = 0.f;
#pragma unroll
            for (int w = 0; w < 8; w++) s += red[w];
            s_gate = 1.0f / (1.0f + expf(-(s + fcb[0])));
        }
        __syncthreads();
    }
    const float gg = s_gate, gm = 1.0f - gg;

    // phase-3 weights (loaded only now — keeps them out of phase-1 live range)
    const float4 wt3 = __ldg(&reinterpret_cast<const float4*>(ltw)[tid]);
    const float4 bt3 = __ldg(&reinterpret_cast<const float4*>(ltb)[tid]);
    const float4 wi3 = __ldg(&reinterpret_cast<const float4*>(liw)[tid]);
    const float4 bi3 = __ldg(&reinterpret_cast<const float4*>(lib)[tid]);

    // ================= phase 3: output blend over 16 stages =================
    float4* out4 = reinterpret_cast<float4*>(out);
    for (int gs = 16; gs < 32; gs++) {
        const int slot = gs % RING;
        const int par  = (gs / RING) & 1;
        mbar_wait(mbb + slot * 8, par);
        const float* buf = ring + slot * STAGE_FLOATS;
        const int p3s = gs - 16;

#pragma unroll
        for (int r = 0; r < 8; r++) {
            const int ridx = p3s * 8 + r;
            const float4 rs = s_rs[ridx];
            const float4 a = reinterpret_cast<const float4*>(buf + r * 1024)[tid];
            const float4 c = reinterpret_cast<const float4*>(buf + 8192 + r * 1024)[tid];
            float4 o;
            o.x = gg * ((a.x - rs.x) * rs.y * wt3.x + bt3.x) + gm * ((c.x - rs.z) * rs.w * wi3.x + bi3.x);
            o.y = gg * ((a.y - rs.x) * rs.y * wt3.y + bt3.y) + gm * ((c.y - rs.z) * rs.w * wi3.y + bi3.y);
            o.z = gg * ((a.z - rs.x) * rs.y * wt3.z + bt3.z) + gm * ((c.z - rs.z) * rs.w * wi3.z + bi3.z);
            o.w = gg * ((a.w - rs.x) * rs.y * wt3.w + bt3.w) + gm * ((c.w - rs.z) * rs.w * wi3.w + bi3.w);
            __stcs(&out4[(size_t)(row0 + ridx) * 256 + tid], o);
        }
        __syncthreads();
        if (tid == 0 && gs + RING < NSTAGE_ALL) {
            const int k = (gs + RING) & 15;
            const uint32_t mb = mbb + slot * 8;
            mbar_expect_tx(mb, 65536);
            const uint32_t dst = ringb + slot * STAGE_FLOATS * 4;
            bulk_g2s(dst,         srcT + k * 8192, 32768, mb);
            bulk_g2s(dst + 32768, srcI + k * 8192, 32768, mb);
        }
    }
}

// ---------------- launch -----------------------------------------------------
extern "C" void kernel_launch(void* const* d_in, const int* in_sizes, int n_in,
                              void* d_out, int out_size)
{
    const float* xt   = (const float*)d_in[0];
    const float* xi   = (const float*)d_in[1];
    const float* ltw  = (const float*)d_in[2];
    const float* ltb  = (const float*)d_in[3];
    const float* liw  = (const float*)d_in[4];
    const float* lib  = (const float*)d_in[5];
    const float* Wa   = (const float*)d_in[6];
    const float* Wab  = (const float*)d_in[7];
    const float* Wq   = (const float*)d_in[8];
    const float* Wqb  = (const float*)d_in[9];
    const float* simw = (const float*)d_in[10];
    const float* simb = (const float*)d_in[11];
    const float* fcw  = (const float*)d_in[12];
    const float* fcb  = (const float*)d_in[13];
    float* out = (float*)d_out;

    static bool attr_set = false;
    if (!attr_set) {
        cudaFuncSetAttribute(k_fused, cudaFuncAttributeMaxDynamicSharedMemorySize, SMEM_BYTES);
        attr_set = true;
    }

    k_fused<<<NCTA, 256, SMEM_BYTES>>>(xt, xi, ltw, ltb, liw, lib,
                                       Wa, Wab, Wq, Wqb, simw, simb, fcw, fcb, out);
}